// round 14
// baseline (speedup 1.0000x reference)
#include <cuda_runtime.h>
#include <cuda_fp16.h>

#define MAX_NODES 100000
#define MAX_EDGES 1600000
#define N_GRAPHS  1024
#define N_FEAT    128
#define HID       64
#define N_CLASSES 16
#define N_CENT    3

#define SCAN_ELEMS 1024
#define MAX_SCAN_BLOCKS 128
#define POOL_CHUNK 128

// ---------------- scratch (no allocation allowed) ----------------
__device__ int   g_indeg   [MAX_NODES];
__device__ int   g_rowstart[MAX_NODES];
__device__ int   g_cursor  [MAX_NODES];
__device__ int   g_csr_src [MAX_EDGES];
__device__ int   g_bsum    [MAX_SCAN_BLOCKS];
__device__ int   g_boff    [MAX_SCAN_BLOCKS];
__device__ float g_dinv[MAX_NODES];
// features fp16, pre-scaled by dinv[node]: hw'[i] = dinv[i] * (X@W)[i]
__device__ __align__(16) __half2 g_hwh[(size_t)MAX_NODES * (HID / 2)];
__device__ __align__(16) float   g_agg [(size_t)MAX_NODES * HID];
__device__ float g_sums[N_GRAPHS * HID];
__device__ float g_cnt [N_GRAPHS];

// ---------------- combined zero: indeg + pool sums/cnt ----------------
__global__ void k_zero_init(int n) {
    int i = blockIdx.x * blockDim.x + threadIdx.x;
    if (i < n) g_indeg[i] = 0;
    if (i < N_GRAPHS * HID) g_sums[i] = 0.0f;
    if (i < N_GRAPHS)       g_cnt[i]  = 0.0f;
}

__global__ void k_count(const int* __restrict__ dst, int E) {
    int e = blockIdx.x * blockDim.x + threadIdx.x;
    if (e < E) atomicAdd(&g_indeg[dst[e]], 1);
}

// ---------------- 3-phase exclusive scan of indeg (fuses dinv) ----------------
__global__ void __launch_bounds__(256) k_scan1(int n) {
    __shared__ int warp_sums[8];
    const int t    = threadIdx.x;
    const int base = blockIdx.x * SCAN_ELEMS + t * 4;

    int v0 = 0, v1 = 0, v2 = 0, v3 = 0;
    if (base + 3 < n) {
        v0 = g_indeg[base];     v1 = g_indeg[base + 1];
        v2 = g_indeg[base + 2]; v3 = g_indeg[base + 3];
    } else {
        if (base     < n) v0 = g_indeg[base];
        if (base + 1 < n) v1 = g_indeg[base + 1];
        if (base + 2 < n) v2 = g_indeg[base + 2];
        if (base + 3 < n) v3 = g_indeg[base + 3];
    }
    int tsum = v0 + v1 + v2 + v3;

    const int lane = t & 31, wid = t >> 5;
    int inc = tsum;
#pragma unroll
    for (int off = 1; off < 32; off <<= 1) {
        int x = __shfl_up_sync(0xffffffffu, inc, off);
        if (lane >= off) inc += x;
    }
    if (lane == 31) warp_sums[wid] = inc;
    __syncthreads();
    if (t < 8) {
        int s = warp_sums[t];
#pragma unroll
        for (int off = 1; off < 8; off <<= 1) {
            int x = __shfl_up_sync(0xffu, s, off);
            if (t >= off) s += x;
        }
        warp_sums[t] = s;
    }
    __syncthreads();

    int excl = inc - tsum + (wid > 0 ? warp_sums[wid - 1] : 0);
    int run = excl;
    if (base     < n) { g_rowstart[base]     = run; run += v0; }
    if (base + 1 < n) { g_rowstart[base + 1] = run; run += v1; }
    if (base + 2 < n) { g_rowstart[base + 2] = run; run += v2; }
    if (base + 3 < n) { g_rowstart[base + 3] = run; run += v3; }
    if (t == 255) g_bsum[blockIdx.x] = warp_sums[7];

    if (base     < n) g_dinv[base]     = rsqrtf((float)(v0 + 1));
    if (base + 1 < n) g_dinv[base + 1] = rsqrtf((float)(v1 + 1));
    if (base + 2 < n) g_dinv[base + 2] = rsqrtf((float)(v2 + 1));
    if (base + 3 < n) g_dinv[base + 3] = rsqrtf((float)(v3 + 1));
}

__global__ void k_scan2(int nb) {
    __shared__ int ws[4];
    const int t = threadIdx.x;               // 128 threads
    int v = (t < nb) ? g_bsum[t] : 0;
    const int lane = t & 31, wid = t >> 5;
    int inc = v;
#pragma unroll
    for (int off = 1; off < 32; off <<= 1) {
        int x = __shfl_up_sync(0xffffffffu, inc, off);
        if (lane >= off) inc += x;
    }
    if (lane == 31) ws[wid] = inc;
    __syncthreads();
    if (t < 4) {
        int s = ws[t];
#pragma unroll
        for (int off = 1; off < 4; off <<= 1) {
            int x = __shfl_up_sync(0xfu, s, off);
            if (t >= off) s += x;
        }
        ws[t] = s;
    }
    __syncthreads();
    int excl = inc - v + (wid > 0 ? ws[wid - 1] : 0);
    if (t < nb) g_boff[t] = excl;
}

__global__ void k_scan3(int n) {
    int i = blockIdx.x * blockDim.x + threadIdx.x;
    if (i < n) {
        int r = g_rowstart[i] + g_boff[i >> 10];
        g_rowstart[i] = r;
        g_cursor[i]   = r;
    }
}

__global__ void k_fill(const int* __restrict__ src, const int* __restrict__ dst, int E) {
    int e = blockIdx.x * blockDim.x + threadIdx.x;
    if (e < E) {
        int pos = atomicAdd(&g_cursor[dst[e]], 1);
        g_csr_src[pos] = src[e];
    }
}

// ---------------- GEMM (pure X@W) + fp16/prescale epilogue ----------------
// g_hwh[n,64] = fp16( dinv[n] * (in[n,K] @ W[K,64]) )   — activation lives in gather now
template <int K, bool FROM_AGG>
__global__ void __launch_bounds__(256) k_gemm(const float* __restrict__ in,
                                              const float* __restrict__ W, int n) {
    constexpr int XS_STRIDE = K + 4;
    __shared__ float Ws[K * HID];
    __shared__ float Xs[64 * XS_STRIDE];

    const int tid  = threadIdx.x;
    const int base = blockIdx.x * 64;

    for (int i = tid; i < K * HID; i += 256) Ws[i] = W[i];

    const float* xin = FROM_AGG ? (const float*)g_agg : in;
    for (int i = tid; i < 64 * (K / 4); i += 256) {
        int r = i / (K / 4), kq = i - r * (K / 4);
        int node = base + r;
        float4 v = make_float4(0.f, 0.f, 0.f, 0.f);
        if (node < n) v = ((const float4*)(xin + (size_t)node * K))[kq];
        float* xr = Xs + r * XS_STRIDE + kq * 4;
        xr[0] = v.x; xr[1] = v.y; xr[2] = v.z; xr[3] = v.w;
    }
    __syncthreads();

    const int cg = tid & 15;
    const int ng = tid >> 4;
    float acc[4][4];
#pragma unroll
    for (int i = 0; i < 4; i++)
#pragma unroll
        for (int j = 0; j < 4; j++) acc[i][j] = 0.0f;

#pragma unroll 4
    for (int k = 0; k < K; k++) {
        float4 w = *(const float4*)(Ws + k * HID + cg * 4);
#pragma unroll
        for (int i = 0; i < 4; i++) {
            float xv = Xs[(ng + 16 * i) * XS_STRIDE + k];
            acc[i][0] = fmaf(xv, w.x, acc[i][0]);
            acc[i][1] = fmaf(xv, w.y, acc[i][1]);
            acc[i][2] = fmaf(xv, w.z, acc[i][2]);
            acc[i][3] = fmaf(xv, w.w, acc[i][3]);
        }
    }

#pragma unroll
    for (int i = 0; i < 4; i++) {
        int node = base + ng + 16 * i;
        if (node < n) {
            float di = g_dinv[node];
            __half2 p0 = __floats2half2_rn(acc[i][0] * di, acc[i][1] * di);
            __half2 p1 = __floats2half2_rn(acc[i][2] * di, acc[i][3] * di);
            uint2 pk;
            pk.x = *(unsigned int*)&p0;
            pk.y = *(unsigned int*)&p1;
            ((uint2*)g_hwh)[(size_t)node * 16 + cg] = pk;
        }
    }
}

// ---------------- gather: agg[d,:] = act( dd * ( hw'[d,:] + sum_e hw'[src_e,:] ) + bias ) ----------------
// ACT: apply bias + relu (layers 1,2). Layer 3: plain (b3 folded in head).
template <bool ACT>
__global__ void __launch_bounds__(256) k_gather(const float* __restrict__ bias, int n) {
    int w = (blockIdx.x * blockDim.x + threadIdx.x) >> 5;
    if (w >= n) return;
    const int lane = threadIdx.x & 31;
    const int half = lane >> 4;
    const int hl   = lane & 15;

    float4 acc  = make_float4(0.f, 0.f, 0.f, 0.f);
    float4 acc2 = make_float4(0.f, 0.f, 0.f, 0.f);
    float4 acc3 = make_float4(0.f, 0.f, 0.f, 0.f);
    float4 acc4 = make_float4(0.f, 0.f, 0.f, 0.f);

    if (half == 0) {                       // self-loop term (hw'[w])
        uint2 r = ((const uint2*)g_hwh)[(size_t)w * 16 + hl];
        float2 f01 = __half22float2(*(__half2*)&r.x);
        float2 f23 = __half22float2(*(__half2*)&r.y);
        acc.x = f01.x; acc.y = f01.y; acc.z = f23.x; acc.w = f23.y;
    }

    const int beg = g_rowstart[w];
    const int end = beg + g_indeg[w];
    int j = beg + half;
    // 4 edges in flight per half-warp (stride 2 within half, 8 per iteration)
    for (; j + 6 < end; j += 8) {
        int s0 = g_csr_src[j];
        int s1 = g_csr_src[j + 2];
        int s2 = g_csr_src[j + 4];
        int s3 = g_csr_src[j + 6];
        uint2 r0 = ((const uint2*)g_hwh)[(size_t)s0 * 16 + hl];
        uint2 r1 = ((const uint2*)g_hwh)[(size_t)s1 * 16 + hl];
        uint2 r2 = ((const uint2*)g_hwh)[(size_t)s2 * 16 + hl];
        uint2 r3 = ((const uint2*)g_hwh)[(size_t)s3 * 16 + hl];
        float2 a01 = __half22float2(*(__half2*)&r0.x);
        float2 a23 = __half22float2(*(__half2*)&r0.y);
        float2 b01 = __half22float2(*(__half2*)&r1.x);
        float2 b23 = __half22float2(*(__half2*)&r1.y);
        float2 c01 = __half22float2(*(__half2*)&r2.x);
        float2 c23 = __half22float2(*(__half2*)&r2.y);
        float2 d01 = __half22float2(*(__half2*)&r3.x);
        float2 d23 = __half22float2(*(__half2*)&r3.y);
        acc.x  += a01.x; acc.y  += a01.y; acc.z  += a23.x; acc.w  += a23.y;
        acc2.x += b01.x; acc2.y += b01.y; acc2.z += b23.x; acc2.w += b23.y;
        acc3.x += c01.x; acc3.y += c01.y; acc3.z += c23.x; acc3.w += c23.y;
        acc4.x += d01.x; acc4.y += d01.y; acc4.z += d23.x; acc4.w += d23.y;
    }
    for (; j < end; j += 2) {
        int s0 = g_csr_src[j];
        uint2 r0 = ((const uint2*)g_hwh)[(size_t)s0 * 16 + hl];
        float2 a01 = __half22float2(*(__half2*)&r0.x);
        float2 a23 = __half22float2(*(__half2*)&r0.y);
        acc.x += a01.x; acc.y += a01.y; acc.z += a23.x; acc.w += a23.y;
    }

    acc.x += acc2.x + acc3.x + acc4.x;
    acc.y += acc2.y + acc3.y + acc4.y;
    acc.z += acc2.z + acc3.z + acc4.z;
    acc.w += acc2.w + acc3.w + acc4.w;
    acc.x += __shfl_xor_sync(0xffffffffu, acc.x, 16);
    acc.y += __shfl_xor_sync(0xffffffffu, acc.y, 16);
    acc.z += __shfl_xor_sync(0xffffffffu, acc.z, 16);
    acc.w += __shfl_xor_sync(0xffffffffu, acc.w, 16);

    if (half == 0) {
        const float dd = g_dinv[w];
        acc.x *= dd; acc.y *= dd; acc.z *= dd; acc.w *= dd;
        if (ACT) {
            float4 b = ((const float4*)bias)[hl];
            acc.x = fmaxf(acc.x + b.x, 0.0f);
            acc.y = fmaxf(acc.y + b.y, 0.0f);
            acc.z = fmaxf(acc.z + b.z, 0.0f);
            acc.w = fmaxf(acc.w + b.w, 0.0f);
        }
        ((float4*)(g_agg + (size_t)w * HID))[hl] = acc;
    }
}

// ---------------- pooling (batch sorted: register run-accumulation) ----------------
__global__ void __launch_bounds__(256) k_pool(const int* __restrict__ batch, int n) {
    int grp   = threadIdx.x >> 6;
    int c     = threadIdx.x & 63;
    int start = (blockIdx.x * 4 + grp) * POOL_CHUNK;
    int end   = min(n, start + POOL_CHUNK);
    if (start >= end) return;

    int cur = batch[start];
    float acc = 0.0f, cacc = 0.0f;
    for (int i = start; i < end; i++) {
        int b = batch[i];
        if (b != cur) {
            atomicAdd(&g_sums[cur * HID + c], acc);
            if (c == 0) atomicAdd(&g_cnt[cur], cacc);
            acc = 0.0f; cacc = 0.0f; cur = b;
        }
        acc  += g_agg[(size_t)i * HID + c];
        cacc += 1.0f;
    }
    atomicAdd(&g_sums[cur * HID + c], acc);
    if (c == 0) atomicAdd(&g_cnt[cur], cacc);
}

// ---------------- head ----------------
__global__ void k_head(const float* __restrict__ b3, const float* __restrict__ C,
                       const float* __restrict__ rbias, float* __restrict__ out) {
    int g = blockIdx.x;
    int tid = threadIdx.x;   // 64 threads
    __shared__ float emb[HID];
    __shared__ float d48[N_CLASSES * N_CENT];
    __shared__ float dpc[N_CLASSES];

    float cnt = fmaxf(g_cnt[g], 1.0f);
    emb[tid] = g_sums[g * HID + tid] / cnt + b3[tid];
    __syncthreads();

    if (tid < N_CLASSES * N_CENT) {
        const float* c = C + tid * HID;
        float acc = 0.0f;
#pragma unroll
        for (int k = 0; k < HID; k++) {
            float df = emb[k] - c[k];
            acc = fmaf(df, df, acc);
        }
        d48[tid] = acc;
    }
    __syncthreads();
    if (tid < N_CLASSES) {
        float m = fminf(d48[tid * 3], fminf(d48[tid * 3 + 1], d48[tid * 3 + 2]));
        dpc[tid] = m;
        out[g * 17 + tid] = -m;
    }
    __syncthreads();
    if (tid == 0) {
        float m = dpc[0];
#pragma unroll
        for (int i = 1; i < N_CLASSES; i++) m = fminf(m, dpc[i]);
        out[g * 17 + 16] = m - rbias[0];
    }
}

// ---------------- launch ----------------
extern "C" void kernel_launch(void* const* d_in, const int* in_sizes, int n_in,
                              void* d_out, int out_size) {
    const float* x     = (const float*)d_in[0];
    const int*   ei    = (const int*)d_in[1];     // JAX default int32
    const int*   batch = (const int*)d_in[2];
    const float* W1    = (const float*)d_in[3];
    const float* b1    = (const float*)d_in[4];
    const float* W2    = (const float*)d_in[5];
    const float* b2    = (const float*)d_in[6];
    const float* W3    = (const float*)d_in[7];
    const float* b3    = (const float*)d_in[8];
    const float* C     = (const float*)d_in[9];
    const float* rb    = (const float*)d_in[10];
    float* out = (float*)d_out;

    int n = in_sizes[0] / N_FEAT;
    int E = in_sizes[1] / 2;
    const int* src = ei;
    const int* dst = ei + E;

    int scanBlocks   = (n + SCAN_ELEMS - 1) / SCAN_ELEMS;
    int gemmBlocks   = (n + 63) / 64;
    int gatherBlocks = (int)(((long long)n * 32 + 255) / 256);
    int poolBlocks   = (n + 4 * POOL_CHUNK - 1) / (4 * POOL_CHUNK);
    int zeroBlocks   = (((n > N_GRAPHS * HID) ? n : N_GRAPHS * HID) + 255) / 256;

    // ---- CSR build + zero ----
    k_zero_init<<<zeroBlocks, 256>>>(n);
    k_count<<<(E + 255) / 256, 256>>>(dst, E);
    k_scan1<<<scanBlocks, 256>>>(n);
    k_scan2<<<1, 128>>>(scanBlocks);
    k_scan3<<<(n + 255) / 256, 256>>>(n);
    k_fill<<<(E + 255) / 256, 256>>>(src, dst, E);

    // ---- layer 1 ----
    k_gemm<N_FEAT, false><<<gemmBlocks, 256>>>(x, W1, n);
    k_gather<true><<<gatherBlocks, 256>>>(b1, n);

    // ---- layer 2 ----
    k_gemm<HID, true><<<gemmBlocks, 256>>>(nullptr, W2, n);
    k_gather<true><<<gatherBlocks, 256>>>(b2, n);

    // ---- layer 3 (b3 folded into head) ----
    k_gemm<HID, true><<<gemmBlocks, 256>>>(nullptr, W3, n);
    k_gather<false><<<gatherBlocks, 256>>>(nullptr, n);

    // ---- pool ----
    k_pool<<<poolBlocks, 256>>>(batch, n);

    // ---- head ----
    k_head<<<N_GRAPHS, HID>>>(b3, C, rb, out);
}

// round 15
// speedup vs baseline: 1.1322x; 1.1322x over previous
#include <cuda_runtime.h>
#include <cuda_fp16.h>

#define MAX_NODES 100000
#define MAX_EDGES 1600000
#define N_GRAPHS  1024
#define N_FEAT    128
#define HID       64
#define N_CLASSES 16
#define N_CENT    3

#define SCAN_ELEMS 1024
#define MAX_SCAN_BLOCKS 128

// ---------------- scratch (no allocation allowed) ----------------
__device__ int   g_indeg   [MAX_NODES];
__device__ int   g_rowstart[MAX_NODES];
__device__ int   g_cursor  [MAX_NODES];
__device__ int   g_csr_src [MAX_EDGES];
__device__ int   g_bsum    [MAX_SCAN_BLOCKS];
__device__ int   g_boff    [MAX_SCAN_BLOCKS];
__device__ float g_dinv[MAX_NODES];
// features fp16, pre-scaled by dinv[node]: hw'[i] = dinv[i] * h[i]
__device__ __align__(16) __half2 g_hwh[(size_t)MAX_NODES * (HID / 2)];
__device__ __align__(16) float   g_agg [(size_t)MAX_NODES * HID];
__device__ float g_sums[N_GRAPHS * HID];
__device__ float g_cnt [N_GRAPHS];

// ---------------- combined zero: indeg + pool sums/cnt ----------------
__global__ void k_zero_init(int n) {
    int i = blockIdx.x * blockDim.x + threadIdx.x;
    if (i < n) g_indeg[i] = 0;
    if (i < N_GRAPHS * HID) g_sums[i] = 0.0f;
    if (i < N_GRAPHS)       g_cnt[i]  = 0.0f;
}

__global__ void k_count(const int* __restrict__ dst, int E) {
    int e = blockIdx.x * blockDim.x + threadIdx.x;
    if (e < E) atomicAdd(&g_indeg[dst[e]], 1);
}

// ---------------- 3-phase exclusive scan of indeg (fuses dinv) ----------------
__global__ void __launch_bounds__(256) k_scan1(int n) {
    __shared__ int warp_sums[8];
    const int t    = threadIdx.x;
    const int base = blockIdx.x * SCAN_ELEMS + t * 4;

    int v0 = 0, v1 = 0, v2 = 0, v3 = 0;
    if (base + 3 < n) {
        v0 = g_indeg[base];     v1 = g_indeg[base + 1];
        v2 = g_indeg[base + 2]; v3 = g_indeg[base + 3];
    } else {
        if (base     < n) v0 = g_indeg[base];
        if (base + 1 < n) v1 = g_indeg[base + 1];
        if (base + 2 < n) v2 = g_indeg[base + 2];
        if (base + 3 < n) v3 = g_indeg[base + 3];
    }
    int tsum = v0 + v1 + v2 + v3;

    const int lane = t & 31, wid = t >> 5;
    int inc = tsum;
#pragma unroll
    for (int off = 1; off < 32; off <<= 1) {
        int x = __shfl_up_sync(0xffffffffu, inc, off);
        if (lane >= off) inc += x;
    }
    if (lane == 31) warp_sums[wid] = inc;
    __syncthreads();
    if (t < 8) {
        int s = warp_sums[t];
#pragma unroll
        for (int off = 1; off < 8; off <<= 1) {
            int x = __shfl_up_sync(0xffu, s, off);
            if (t >= off) s += x;
        }
        warp_sums[t] = s;
    }
    __syncthreads();

    int excl = inc - tsum + (wid > 0 ? warp_sums[wid - 1] : 0);
    int run = excl;
    if (base     < n) { g_rowstart[base]     = run; run += v0; }
    if (base + 1 < n) { g_rowstart[base + 1] = run; run += v1; }
    if (base + 2 < n) { g_rowstart[base + 2] = run; run += v2; }
    if (base + 3 < n) { g_rowstart[base + 3] = run; run += v3; }
    if (t == 255) g_bsum[blockIdx.x] = warp_sums[7];

    if (base     < n) g_dinv[base]     = rsqrtf((float)(v0 + 1));
    if (base + 1 < n) g_dinv[base + 1] = rsqrtf((float)(v1 + 1));
    if (base + 2 < n) g_dinv[base + 2] = rsqrtf((float)(v2 + 1));
    if (base + 3 < n) g_dinv[base + 3] = rsqrtf((float)(v3 + 1));
}

__global__ void k_scan2(int nb) {
    __shared__ int ws[4];
    const int t = threadIdx.x;               // 128 threads
    int v = (t < nb) ? g_bsum[t] : 0;
    const int lane = t & 31, wid = t >> 5;
    int inc = v;
#pragma unroll
    for (int off = 1; off < 32; off <<= 1) {
        int x = __shfl_up_sync(0xffffffffu, inc, off);
        if (lane >= off) inc += x;
    }
    if (lane == 31) ws[wid] = inc;
    __syncthreads();
    if (t < 4) {
        int s = ws[t];
#pragma unroll
        for (int off = 1; off < 4; off <<= 1) {
            int x = __shfl_up_sync(0xfu, s, off);
            if (t >= off) s += x;
        }
        ws[t] = s;
    }
    __syncthreads();
    int excl = inc - v + (wid > 0 ? ws[wid - 1] : 0);
    if (t < nb) g_boff[t] = excl;
}

__global__ void k_scan3(int n) {
    int i = blockIdx.x * blockDim.x + threadIdx.x;
    if (i < n) {
        int r = g_rowstart[i] + g_boff[i >> 10];
        g_rowstart[i] = r;
        g_cursor[i]   = r;
    }
}

__global__ void k_fill(const int* __restrict__ src, const int* __restrict__ dst, int E) {
    int e = blockIdx.x * blockDim.x + threadIdx.x;
    if (e < E) {
        int pos = atomicAdd(&g_cursor[dst[e]], 1);
        g_csr_src[pos] = src[e];
    }
}

// ---------------- GEMM v2 + fp16/prescale epilogue (R13 winner) ----------------
// g_hwh[n,64] = fp16( dinv[n] * (act(in[n,K]) @ W[K,64]) )
template <int K, bool FROM_AGG, bool ACT>
__global__ void __launch_bounds__(256) k_gemm(const float* __restrict__ in,
                                              const float* __restrict__ W,
                                              const float* __restrict__ bias, int n) {
    constexpr int XS_STRIDE = K + 4;
    __shared__ float Ws[K * HID];
    __shared__ float Xs[64 * XS_STRIDE];
    __shared__ float Bs[K];

    const int tid  = threadIdx.x;
    const int base = blockIdx.x * 64;

    for (int i = tid; i < K * HID; i += 256) Ws[i] = W[i];
    if (ACT) for (int i = tid; i < K; i += 256) Bs[i] = bias[i];

    const float* xin = FROM_AGG ? (const float*)g_agg : in;
    for (int i = tid; i < 64 * (K / 4); i += 256) {
        int r = i / (K / 4), kq = i - r * (K / 4);
        int node = base + r;
        float4 v = make_float4(0.f, 0.f, 0.f, 0.f);
        if (node < n) v = ((const float4*)(xin + (size_t)node * K))[kq];
        float* xr = Xs + r * XS_STRIDE + kq * 4;
        xr[0] = v.x; xr[1] = v.y; xr[2] = v.z; xr[3] = v.w;
    }
    __syncthreads();

    const int cg = tid & 15;
    const int ng = tid >> 4;
    float acc[4][4];
#pragma unroll
    for (int i = 0; i < 4; i++)
#pragma unroll
        for (int j = 0; j < 4; j++) acc[i][j] = 0.0f;

#pragma unroll 4
    for (int k = 0; k < K; k++) {
        float4 w = *(const float4*)(Ws + k * HID + cg * 4);
        float xv[4];
#pragma unroll
        for (int i = 0; i < 4; i++) {
            float v = Xs[(ng + 16 * i) * XS_STRIDE + k];
            if (ACT) v = fmaxf(v + Bs[k], 0.0f);
            xv[i] = v;
        }
#pragma unroll
        for (int i = 0; i < 4; i++) {
            acc[i][0] = fmaf(xv[i], w.x, acc[i][0]);
            acc[i][1] = fmaf(xv[i], w.y, acc[i][1]);
            acc[i][2] = fmaf(xv[i], w.z, acc[i][2]);
            acc[i][3] = fmaf(xv[i], w.w, acc[i][3]);
        }
    }

#pragma unroll
    for (int i = 0; i < 4; i++) {
        int node = base + ng + 16 * i;
        if (node < n) {
            float di = g_dinv[node];
            __half2 p0 = __floats2half2_rn(acc[i][0] * di, acc[i][1] * di);
            __half2 p1 = __floats2half2_rn(acc[i][2] * di, acc[i][3] * di);
            uint2 pk;
            pk.x = *(unsigned int*)&p0;
            pk.y = *(unsigned int*)&p1;
            ((uint2*)g_hwh)[(size_t)node * 16 + cg] = pk;
        }
    }
}

// ---------------- shared gather core (R13 2-in-flight pattern) ----------------
__device__ __forceinline__ float4 gather_row(int w, int lane, int half, int hl) {
    float4 acc  = make_float4(0.f, 0.f, 0.f, 0.f);
    float4 acc2 = make_float4(0.f, 0.f, 0.f, 0.f);

    if (half == 0) {                       // self-loop term (hw'[w])
        uint2 r = ((const uint2*)g_hwh)[(size_t)w * 16 + hl];
        float2 f01 = __half22float2(*(__half2*)&r.x);
        float2 f23 = __half22float2(*(__half2*)&r.y);
        acc.x = f01.x; acc.y = f01.y; acc.z = f23.x; acc.w = f23.y;
    }

    const int beg = g_rowstart[w];
    const int end = beg + g_indeg[w];
    int j = beg + half;
    for (; j + 2 < end; j += 4) {          // two edges in flight per half-warp
        int s0 = g_csr_src[j];
        int s1 = g_csr_src[j + 2];
        uint2 r0 = ((const uint2*)g_hwh)[(size_t)s0 * 16 + hl];
        uint2 r1 = ((const uint2*)g_hwh)[(size_t)s1 * 16 + hl];
        float2 a01 = __half22float2(*(__half2*)&r0.x);
        float2 a23 = __half22float2(*(__half2*)&r0.y);
        float2 b01 = __half22float2(*(__half2*)&r1.x);
        float2 b23 = __half22float2(*(__half2*)&r1.y);
        acc.x  += a01.x; acc.y  += a01.y; acc.z  += a23.x; acc.w  += a23.y;
        acc2.x += b01.x; acc2.y += b01.y; acc2.z += b23.x; acc2.w += b23.y;
    }
    if (j < end) {
        int s0 = g_csr_src[j];
        uint2 r0 = ((const uint2*)g_hwh)[(size_t)s0 * 16 + hl];
        float2 a01 = __half22float2(*(__half2*)&r0.x);
        float2 a23 = __half22float2(*(__half2*)&r0.y);
        acc.x += a01.x; acc.y += a01.y; acc.z += a23.x; acc.w += a23.y;
    }

    acc.x += acc2.x; acc.y += acc2.y; acc.z += acc2.z; acc.w += acc2.w;
    acc.x += __shfl_xor_sync(0xffffffffu, acc.x, 16);
    acc.y += __shfl_xor_sync(0xffffffffu, acc.y, 16);
    acc.z += __shfl_xor_sync(0xffffffffu, acc.z, 16);
    acc.w += __shfl_xor_sync(0xffffffffu, acc.w, 16);
    return acc;
}

// layers 1,2: agg[w,:] = dd * gathered   (fp32, consumed by next GEMM)
__global__ void __launch_bounds__(256) k_gather(int n) {
    int w = (blockIdx.x * blockDim.x + threadIdx.x) >> 5;
    if (w >= n) return;
    const int lane = threadIdx.x & 31;
    const int half = lane >> 4;
    const int hl   = lane & 15;

    float4 acc = gather_row(w, lane, half, hl);

    if (half == 0) {
        const float dd = g_dinv[w];
        acc.x *= dd; acc.y *= dd; acc.z *= dd; acc.w *= dd;
        ((float4*)(g_agg + (size_t)w * HID))[hl] = acc;
    }
}

// layer 3: fused gather + mean-pool accumulate (no agg round-trip, no k_pool)
__global__ void __launch_bounds__(256) k_gather_pool(const int* __restrict__ batch, int n) {
    int w = (blockIdx.x * blockDim.x + threadIdx.x) >> 5;
    if (w >= n) return;
    const int lane = threadIdx.x & 31;
    const int half = lane >> 4;
    const int hl   = lane & 15;

    float4 acc = gather_row(w, lane, half, hl);

    if (half == 0) {
        const float dd = g_dinv[w];
        int b = batch[w];
        float* s = g_sums + b * HID + hl * 4;
        atomicAdd(s,     acc.x * dd);
        atomicAdd(s + 1, acc.y * dd);
        atomicAdd(s + 2, acc.z * dd);
        atomicAdd(s + 3, acc.w * dd);
        if (hl == 0) atomicAdd(&g_cnt[b], 1.0f);
    }
}

// ---------------- head ----------------
__global__ void k_head(const float* __restrict__ b3, const float* __restrict__ C,
                       const float* __restrict__ rbias, float* __restrict__ out) {
    int g = blockIdx.x;
    int tid = threadIdx.x;   // 64 threads
    __shared__ float emb[HID];
    __shared__ float d48[N_CLASSES * N_CENT];
    __shared__ float dpc[N_CLASSES];

    float cnt = fmaxf(g_cnt[g], 1.0f);
    emb[tid] = g_sums[g * HID + tid] / cnt + b3[tid];
    __syncthreads();

    if (tid < N_CLASSES * N_CENT) {
        const float* c = C + tid * HID;
        float acc = 0.0f;
#pragma unroll
        for (int k = 0; k < HID; k++) {
            float df = emb[k] - c[k];
            acc = fmaf(df, df, acc);
        }
        d48[tid] = acc;
    }
    __syncthreads();
    if (tid < N_CLASSES) {
        float m = fminf(d48[tid * 3], fminf(d48[tid * 3 + 1], d48[tid * 3 + 2]));
        dpc[tid] = m;
        out[g * 17 + tid] = -m;
    }
    __syncthreads();
    if (tid == 0) {
        float m = dpc[0];
#pragma unroll
        for (int i = 1; i < N_CLASSES; i++) m = fminf(m, dpc[i]);
        out[g * 17 + 16] = m - rbias[0];
    }
}

// ---------------- launch ----------------
extern "C" void kernel_launch(void* const* d_in, const int* in_sizes, int n_in,
                              void* d_out, int out_size) {
    const float* x     = (const float*)d_in[0];
    const int*   ei    = (const int*)d_in[1];     // JAX default int32
    const int*   batch = (const int*)d_in[2];
    const float* W1    = (const float*)d_in[3];
    const float* b1    = (const float*)d_in[4];
    const float* W2    = (const float*)d_in[5];
    const float* b2    = (const float*)d_in[6];
    const float* W3    = (const float*)d_in[7];
    const float* b3    = (const float*)d_in[8];
    const float* C     = (const float*)d_in[9];
    const float* rb    = (const float*)d_in[10];
    float* out = (float*)d_out;

    int n = in_sizes[0] / N_FEAT;
    int E = in_sizes[1] / 2;
    const int* src = ei;
    const int* dst = ei + E;

    int scanBlocks   = (n + SCAN_ELEMS - 1) / SCAN_ELEMS;
    int gemmBlocks   = (n + 63) / 64;
    int gatherBlocks = (int)(((long long)n * 32 + 255) / 256);
    int zeroBlocks   = (((n > N_GRAPHS * HID) ? n : N_GRAPHS * HID) + 255) / 256;

    // ---- CSR build + zero ----
    k_zero_init<<<zeroBlocks, 256>>>(n);
    k_count<<<(E + 255) / 256, 256>>>(dst, E);
    k_scan1<<<scanBlocks, 256>>>(n);
    k_scan2<<<1, 128>>>(scanBlocks);
    k_scan3<<<(n + 255) / 256, 256>>>(n);
    k_fill<<<(E + 255) / 256, 256>>>(src, dst, E);

    // ---- layer 1 ----
    k_gemm<N_FEAT, false, false><<<gemmBlocks, 256>>>(x, W1, nullptr, n);
    k_gather<<<gatherBlocks, 256>>>(n);

    // ---- layer 2 (bias1+relu folded into GEMM input) ----
    k_gemm<HID, true, true><<<gemmBlocks, 256>>>(nullptr, W2, b1, n);
    k_gather<<<gatherBlocks, 256>>>(n);

    // ---- layer 3 (bias2+relu folded; gather fused with pool) ----
    k_gemm<HID, true, true><<<gemmBlocks, 256>>>(nullptr, W3, b2, n);
    k_gather_pool<<<gatherBlocks, 256>>>(batch, n);

    // ---- head (b3 folded here) ----
    k_head<<<N_GRAPHS, HID>>>(b3, C, rb, out);
}